// round 2
// baseline (speedup 1.0000x reference)
#include <cuda_runtime.h>
#include <math.h>

// Problem constants (fixed by the dataset)
#define Bsz 1024
#define Tn  200
#define LXn 190
#define LYn 50
#define Hd  256
#define XDd 64
#define YDd 64

#define GRID 128
#define NTHR 256
#define KC   32

typedef unsigned long long ull;

// ---------------- device scratch (module-static, allowed) -------------------
__device__ float g_h [Bsz*Hd];
__device__ float g_s [Bsz*Hd];
__device__ float g_tf[Bsz*Hd];
__device__ float g_hi[Bsz*Hd];
__device__ float g_tu[Bsz*Hd];
__device__ float g_tr[Bsz*Hd];
__device__ float g_u [Bsz*Hd];
__device__ float g_c1[Bsz*Hd];
__device__ float g_c2[Bsz*Hd];
__device__ float g_tn[Bsz*Hd];
__device__ float g_yb[(size_t)LYn*Bsz*Hd];   // saved new_y at the 50 query steps
__device__ float g_to[(size_t)LYn*Bsz*Hd];   // out-MLP hidden
__device__ float g_dt[Tn];
__device__ int   g_obs[Tn];
__device__ int   g_qm [Tn];
__device__ unsigned g_cnt;
__device__ unsigned g_gen;

// ---------------- packed f32x2 helpers --------------------------------------
__device__ __forceinline__ ull fma2(ull a, ull b, ull c) {
    ull d;
    asm("fma.rn.f32x2 %0, %1, %2, %3;" : "=l"(d) : "l"(a), "l"(b), "l"(c));
    return d;
}
__device__ __forceinline__ ull dup2(float x) {
    ull d;
    asm("mov.b64 %0, {%1, %1};" : "=l"(d) : "f"(x));
    return d;
}
__device__ __forceinline__ void unpk(ull u, float& lo, float& hi) {
    asm("mov.b64 {%0, %1}, %2;" : "=f"(lo), "=f"(hi) : "l"(u));
}

// ---------------- grid barrier (all 128 CTAs resident) ----------------------
__device__ __forceinline__ void gbar() {
    __syncthreads();
    if (threadIdx.x == 0) {
        __threadfence();
        volatile unsigned* vg = &g_gen;
        unsigned gen = *vg;
        if (atomicAdd(&g_cnt, 1u) == GRID - 1u) {
            atomicExch(&g_cnt, 0u);
            __threadfence();
            atomicExch((unsigned*)&g_gen, gen + 1u);
        } else {
            while (*vg == gen) { }
        }
        __threadfence();
    }
    __syncthreads();
}

// ---------------- A-operand sources ------------------------------------------
enum { SRC_H, SRC_TF, SRC_GI, SRC_TU, SRC_TR, SRC_CC, SRC_TN, SRC_YB, SRC_TO };
enum { EPI_TANH, EPI_HI, EPI_U, EPI_R, EPI_NS, EPI_OUT };

__device__ __forceinline__ float loadA(int src, int m, int k, int obs,
                                       const float* __restrict__ xd,
                                       const float* __restrict__ xm) {
    switch (src) {
    case SRC_H:  return __ldcg(g_h  + m*Hd + k);
    case SRC_TF: return __ldcg(g_tf + m*Hd + k);
    case SRC_GI:
        if (k < Hd)   return __ldcg(g_hi + m*Hd + k);
        if (k < 2*Hd) return __ldcg(g_s  + m*Hd + (k - Hd));
        else {
            if (obs < 0) return 0.0f;
            int o = (m*LXn + obs)*XDd + (k - 2*Hd);
            return __ldg(xd + o) * __ldg(xm + o);
        }
    case SRC_TU: return __ldcg(g_tu + m*Hd + k);
    case SRC_TR: return __ldcg(g_tr + m*Hd + k);
    case SRC_CC:
        if (k < Hd)   return __ldcg(g_c1 + m*Hd + k);
        if (k < 2*Hd) return __ldcg(g_c2 + m*Hd + (k - Hd));
        else {
            if (obs < 0) return 0.0f;
            int o = (m*LXn + obs)*XDd + (k - 2*Hd);
            return __ldg(xd + o) * __ldg(xm + o);
        }
    case SRC_TN: return __ldcg(g_tn + m*Hd + k);
    case SRC_YB: return __ldcg(g_yb + (size_t)m*Hd + k);
    default:     return __ldcg(g_to + (size_t)m*Hd + k);
    }
}

// ---------------- one 32x64 output tile --------------------------------------
// C[m0:m0+32, n0:n0+64] = A[m, 0:K] * W[0:K, n0:n0+64]  (+bias, +epilogue)
__device__ __noinline__ void tile_gemm(float* As, float* Bs,
                                       int src, int m0, int n0,
                                       const float* __restrict__ W, int ldw,
                                       const float* __restrict__ bias, int K,
                                       int epi, int obs, float dt, int q,
                                       const float* __restrict__ xd,
                                       const float* __restrict__ xm,
                                       float* __restrict__ dout)
{
    const int tid = threadIdx.x;
    const int tx = tid & 15, ty = tid >> 4;   // compute map: cols tx*4.., rows 2*ty..
    const int ka = tid & 31, ma = tid >> 5;   // A-load map

    ull acc0 = 0ULL, acc1 = 0ULL, acc2 = 0ULL, acc3 = 0ULL;

    float  aR[4];
    float4 bR[2];
    // prefetch chunk 0
#pragma unroll
    for (int p = 0; p < 4; p++)
        aR[p] = loadA(src, m0 + ma + p*8, ka, obs, xd, xm);
#pragma unroll
    for (int p = 0; p < 2; p++) {
        int e = tid + p*NTHR; int n4 = e & 15, kk = e >> 4;
        bR[p] = __ldg((const float4*)(W + (size_t)kk*ldw + n0 + n4*4));
    }

    for (int kb = 0; kb < K; kb += KC) {
        __syncthreads();
#pragma unroll
        for (int p = 0; p < 4; p++) As[ka*34 + ma + p*8] = aR[p];
#pragma unroll
        for (int p = 0; p < 2; p++) {
            int e = tid + p*NTHR; int n4 = e & 15, kk = e >> 4;
            *(float4*)&Bs[kk*64 + n4*4] = bR[p];
        }
        __syncthreads();
        int kn = kb + KC;
        if (kn < K) {
#pragma unroll
            for (int p = 0; p < 4; p++)
                aR[p] = loadA(src, m0 + ma + p*8, kn + ka, obs, xd, xm);
#pragma unroll
            for (int p = 0; p < 2; p++) {
                int e = tid + p*NTHR; int n4 = e & 15, kk = e >> 4;
                bR[p] = __ldg((const float4*)(W + (size_t)(kn + kk)*ldw + n0 + n4*4));
            }
        }
#pragma unroll
        for (int k = 0; k < KC; k++) {
            ull a2 = *(const ull*)&As[k*34 + 2*ty];
            float4 b4 = *(const float4*)&Bs[k*64 + tx*4];
            acc0 = fma2(a2, dup2(b4.x), acc0);
            acc1 = fma2(a2, dup2(b4.y), acc1);
            acc2 = fma2(a2, dup2(b4.z), acc2);
            acc3 = fma2(a2, dup2(b4.w), acc3);
        }
    }

    // epilogue
    float v[2][4];
    unpk(acc0, v[0][0], v[1][0]);
    unpk(acc1, v[0][1], v[1][1]);
    unpk(acc2, v[0][2], v[1][2]);
    unpk(acc3, v[0][3], v[1][3]);

#pragma unroll
    for (int r = 0; r < 2; r++) {
        int m = m0 + 2*ty + r;
#pragma unroll
        for (int c = 0; c < 4; c++) {
            int n = n0 + tx*4 + c;
            float val = v[r][c] + __ldg(bias + n);
            switch (epi) {
            case EPI_TANH:
                __stcg(dout + (size_t)m*Hd + n, tanhf(val));
                break;
            case EPI_HI:
                __stcg(g_hi + m*Hd + n, __ldcg(g_h + m*Hd + n) + dt*val);
                break;
            case EPI_U:
                __stcg(g_u + m*Hd + n, 1.0f/(1.0f + expf(-val)));
                break;
            case EPI_R: {
                float rr = 1.0f/(1.0f + expf(-val));
                __stcg(g_c1 + m*Hd + n, __ldcg(g_hi + m*Hd + n) * rr);
                __stcg(g_c2 + m*Hd + n, __ldcg(g_s  + m*Hd + n) * rr);
            } break;
            case EPI_NS: {
                if (n < Hd) {
                    float uu = __ldcg(g_u  + m*Hd + n);
                    float hi = __ldcg(g_hi + m*Hd + n);
                    float ny = (1.0f - uu)*val + uu*hi;
                    __stcg(g_h + m*Hd + n, ny);
                    if (q >= 0)
                        __stcg(g_yb + ((size_t)q*Bsz + m)*Hd + n, ny);
                } else {
                    int nn = n - Hd;
                    float uu = __ldcg(g_u + m*Hd + nn);
                    float sv = __ldcg(g_s + m*Hd + nn);
                    float nstd = fabsf((1.0f - uu)*fabsf(val) + uu*sv);
                    __stcg(g_s + m*Hd + nn, nstd);
                }
            } break;
            case EPI_OUT: {
                int b = m & (Bsz - 1), qq = m >> 10;
                dout[((size_t)b*LYn + qq)*YDd + n] = val;
            } break;
            }
        }
    }
}

// ---------------- init: dt / obs-slot / query maps ---------------------------
__global__ void init_kernel(const float* __restrict__ x_time,
                            const int* __restrict__ x_idx,
                            const int* __restrict__ y_idx) {
    int tid = threadIdx.x;
    for (int t = tid; t < Tn; t += blockDim.x) { g_obs[t] = -1; g_qm[t] = -1; }
    __syncthreads();
    for (int i = tid; i < LXn; i += blockDim.x) g_obs[x_idx[i]] = i;
    for (int j = tid; j < LYn; j += blockDim.x) g_qm[y_idx[j]] = j;
    __syncthreads();
    for (int t = tid; t < Tn; t += blockDim.x) {
        float d;
        float tlast = x_time[Tn - 1];
        if (t == 0)      d = tlast - (tlast + 0.01f);   // ti - prev_ti at step 0
        else if (t == 1) d = tlast - x_time[0];
        else             d = x_time[t - 2] - x_time[t - 1];
        g_dt[t] = d;
    }
}

// ---------------- persistent recurrence kernel -------------------------------
__global__ void __launch_bounds__(NTHR, 1)
recur_kernel(const float* __restrict__ xd, const float* __restrict__ xm,
             const float* ug_w1, const float* ug_b1, const float* ug_w2, const float* ug_b2,
             const float* rg_w1, const float* rg_b1, const float* rg_w2, const float* rg_b2,
             const float* ns_w1, const float* ns_b1, const float* ns_w2, const float* ns_b2,
             const float* out_w1, const float* out_b1, const float* out_w2, const float* out_b2,
             const float* f_w1, const float* f_b1, const float* f_w2, const float* f_b2,
             float* __restrict__ out)
{
    __shared__ float As[KC*34];
    __shared__ float Bs[KC*64];

    // zero initial state
    for (int i = blockIdx.x*NTHR + threadIdx.x; i < Bsz*Hd; i += GRID*NTHR) {
        __stcg(g_h + i, 0.0f);
        __stcg(g_s + i, 0.0f);
    }
    gbar();

    for (int t = 0; t < Tn; t++) {
        int obs = g_obs[t];
        int q   = g_qm[t];
        float dt = g_dt[t];

        // S1: t_f = tanh(h @ f_w1 + f_b1)                     [128 tiles]
        for (int tl = blockIdx.x; tl < 128; tl += GRID)
            tile_gemm(As, Bs, SRC_H, (tl >> 2)*32, (tl & 3)*64,
                      f_w1, Hd, f_b1, Hd, EPI_TANH, obs, dt, q, xd, xm, g_tf);
        gbar();

        // S2: hi = h + dt*(t_f @ f_w2 + f_b2)                 [128 tiles]
        for (int tl = blockIdx.x; tl < 128; tl += GRID)
            tile_gemm(As, Bs, SRC_TF, (tl >> 2)*32, (tl & 3)*64,
                      f_w2, Hd, f_b2, Hd, EPI_HI, obs, dt, q, xd, xm, g_hi);
        gbar();

        // S3: t_u / t_r = tanh([hi,s,x] @ {ug,rg}_w1 + b)     [256 tiles]
        for (int tl = blockIdx.x; tl < 256; tl += GRID) {
            int hh = tl >> 7, t2 = tl & 127;
            tile_gemm(As, Bs, SRC_GI, (t2 >> 2)*32, (t2 & 3)*64,
                      hh ? rg_w1 : ug_w1, Hd, hh ? rg_b1 : ug_b1, 2*Hd + XDd,
                      EPI_TANH, obs, dt, q, xd, xm, hh ? g_tr : g_tu);
        }
        gbar();

        // S4: u = sig(t_u@ug_w2+b) ; r-side writes c1=hi*r, c2=s*r  [256 tiles]
        for (int tl = blockIdx.x; tl < 256; tl += GRID) {
            int hh = tl >> 7, t2 = tl & 127;
            tile_gemm(As, Bs, hh ? SRC_TR : SRC_TU, (t2 >> 2)*32, (t2 & 3)*64,
                      hh ? rg_w2 : ug_w2, Hd, hh ? rg_b2 : ug_b2, Hd,
                      hh ? EPI_R : EPI_U, obs, dt, q, xd, xm, g_u);
        }
        gbar();

        // S5: t_n = tanh([c1,c2,x] @ ns_w1 + b)               [128 tiles]
        for (int tl = blockIdx.x; tl < 128; tl += GRID)
            tile_gemm(As, Bs, SRC_CC, (tl >> 2)*32, (tl & 3)*64,
                      ns_w1, Hd, ns_b1, 2*Hd + XDd, EPI_TANH, obs, dt, q, xd, xm, g_tn);
        gbar();

        // S6: ns = t_n @ ns_w2 + b (N=512), gated state update [256 tiles]
        for (int tl = blockIdx.x; tl < 256; tl += GRID)
            tile_gemm(As, Bs, SRC_TN, (tl >> 3)*32, (tl & 7)*64,
                      ns_w2, 2*Hd, ns_b2, Hd, EPI_NS, obs, dt, q, xd, xm, g_h);
        gbar();
    }

    // O1: t_o = tanh(yb @ out_w1 + b1), M = 50*1024            [6400 tiles]
    for (int tl = blockIdx.x; tl < (LYn*Bsz/32)*4; tl += GRID)
        tile_gemm(As, Bs, SRC_YB, (tl >> 2)*32, (tl & 3)*64,
                  out_w1, Hd, out_b1, Hd, EPI_TANH, -1, 0.0f, -1, xd, xm, g_to);
    gbar();

    // O2: out = t_o @ out_w2 + b2  (N=64)                      [1600 tiles]
    for (int tl = blockIdx.x; tl < LYn*Bsz/32; tl += GRID)
        tile_gemm(As, Bs, SRC_TO, tl*32, 0,
                  out_w2, YDd, out_b2, Hd, EPI_OUT, -1, 0.0f, -1, xd, xm, out);
}

// ---------------- launch ------------------------------------------------------
extern "C" void kernel_launch(void* const* d_in, const int* in_sizes, int n_in,
                              void* d_out, int out_size) {
    (void)in_sizes; (void)n_in; (void)out_size;
    const float* xd  = (const float*)d_in[0];
    const float* xm  = (const float*)d_in[1];
    const float* xt  = (const float*)d_in[2];
    const int*   xti = (const int*)d_in[3];
    const int*   yti = (const int*)d_in[4];

    init_kernel<<<1, 256>>>(xt, xti, yti);

    recur_kernel<<<GRID, NTHR>>>(
        xd, xm,
        (const float*)d_in[5],  (const float*)d_in[6],  (const float*)d_in[7],  (const float*)d_in[8],
        (const float*)d_in[9],  (const float*)d_in[10], (const float*)d_in[11], (const float*)d_in[12],
        (const float*)d_in[13], (const float*)d_in[14], (const float*)d_in[15], (const float*)d_in[16],
        (const float*)d_in[17], (const float*)d_in[18], (const float*)d_in[19], (const float*)d_in[20],
        (const float*)d_in[21], (const float*)d_in[22], (const float*)d_in[23], (const float*)d_in[24],
        (float*)d_out);
}